// round 1
// baseline (speedup 1.0000x reference)
#include <cuda_runtime.h>
#include <math.h>

#define Bb      8
#define HW      1024
#define Cc      512
#define NSPLIT  16
#define ROWS_PER_SPLIT (HW / NSPLIT)   // 64

// Scratch (__device__ globals per allocation rules). Every element is fully
// overwritten on every launch -> graph replays are deterministic.
__device__ float g_partial[Bb][NSPLIT][Cc];     // 256 KB
__device__ float g_ksum[Bb][Cc];
__device__ __align__(16) float g_u[Bb][Cc];
__device__ float g_dot[Bb * HW];

// ---------------------------------------------------------------------------
// Kernel 1: partial column sums of x.  grid (Bb, NSPLIT), block Cc threads.
// Thread c sums 64 rows (coalesced: consecutive threads -> consecutive c).
// ---------------------------------------------------------------------------
__global__ void k_colsum(const float* __restrict__ x) {
    const int b = blockIdx.x;
    const int s = blockIdx.y;
    const int c = threadIdx.x;
    const float* base = x + ((size_t)b * HW + (size_t)s * ROWS_PER_SPLIT) * Cc + c;
    float acc = 0.0f;
#pragma unroll 8
    for (int p = 0; p < ROWS_PER_SPLIT; ++p)
        acc += base[(size_t)p * Cc];
    g_partial[b][s][c] = acc;
}

// ---------------------------------------------------------------------------
// Kernel 2a: per batch b:
//   Xsum  = sum of partials
//   XRsum = Xsum @ conv_w^T + HW*conv_b + Xsum
//   Ksum  = XRsum @ k_w^T + HW*k_b      -> global
// Warp-per-output-row matvec: lanes stride over c (coalesced weight reads).
// grid Bb, block 512 (16 warps x 32 rows each).
// ---------------------------------------------------------------------------
__global__ void k_stage1(const float* __restrict__ conv_w,
                         const float* __restrict__ conv_b,
                         const float* __restrict__ k_w,
                         const float* __restrict__ k_b) {
    __shared__ float xsum[Cc];
    __shared__ float xr[Cc];
    const int b = blockIdx.x;
    const int t = threadIdx.x;
    const int warp = t >> 5, lane = t & 31;

    float a = 0.0f;
#pragma unroll
    for (int s = 0; s < NSPLIT; ++s) a += g_partial[b][s][t];
    xsum[t] = a;
    __syncthreads();

    for (int r = 0; r < 32; ++r) {
        const int o = warp * 32 + r;
        const float* wrow = conv_w + (size_t)o * Cc;
        float p = 0.0f;
#pragma unroll
        for (int k = 0; k < 16; ++k)
            p += wrow[lane + 32 * k] * xsum[lane + 32 * k];
#pragma unroll
        for (int off = 16; off; off >>= 1)
            p += __shfl_xor_sync(0xffffffffu, p, off);
        if (lane == 0)
            xr[o] = p + (float)HW * conv_b[o] + xsum[o];
    }
    __syncthreads();

    for (int r = 0; r < 32; ++r) {
        const int o = warp * 32 + r;
        const float* wrow = k_w + (size_t)o * Cc;
        float p = 0.0f;
#pragma unroll
        for (int k = 0; k < 16; ++k)
            p += wrow[lane + 32 * k] * xr[lane + 32 * k];
#pragma unroll
        for (int off = 16; off; off >>= 1)
            p += __shfl_xor_sync(0xffffffffu, p, off);
        if (lane == 0)
            g_ksum[b][o] = p + (float)HW * k_b[o];
    }
}

// ---------------------------------------------------------------------------
// Kernel 2b: per batch b:
//   v = KsumAll - Ksum[b]
//   w[c] = sum_o q_w[o,c] * v[o]        (transposed matvec: coalesced over c)
//   u[c] = sum_o conv_w[o,c] * w[o] + w[c]   -> global
// grid Bb, block 512 (thread = channel c).
// ---------------------------------------------------------------------------
__global__ void k_stage2(const float* __restrict__ conv_w,
                         const float* __restrict__ q_w) {
    __shared__ float v[Cc];
    __shared__ float w[Cc];
    const int b = blockIdx.x;
    const int t = threadIdx.x;

    float a = 0.0f;
#pragma unroll
    for (int b2 = 0; b2 < Bb; ++b2) a += g_ksum[b2][t];
    v[t] = a - g_ksum[b][t];
    __syncthreads();

    float acc = 0.0f;
#pragma unroll 8
    for (int o = 0; o < Cc; ++o)
        acc += q_w[(size_t)o * Cc + t] * v[o];
    w[t] = acc;
    __syncthreads();

    float acc2 = 0.0f;
#pragma unroll 8
    for (int o = 0; o < Cc; ++o)
        acc2 += conv_w[(size_t)o * Cc + t] * w[o];
    g_u[b][t] = acc2 + w[t];
}

// ---------------------------------------------------------------------------
// Kernel 3: dot[b,i] = x[b,i] . u_b.  grid (8 chunks, Bb), block 256.
// x resident in L2 after kernel 1 (16 MB << 126 MB).  float4 loads,
// warp-per-row (16 rows/warp), shuffle reduce.
// ---------------------------------------------------------------------------
__global__ void k_dot(const float* __restrict__ x) {
    __shared__ float4 u4[Cc / 4];   // 128 float4
    const int b = blockIdx.y;
    const int chunk = blockIdx.x;   // 0..7, 128 rows each
    const int t = threadIdx.x;
    const int warp = t >> 5, lane = t & 31;

    if (t < Cc / 4)
        u4[t] = reinterpret_cast<const float4*>(g_u[b])[t];
    __syncthreads();

    const float4* x4 = reinterpret_cast<const float4*>(x)
                     + ((size_t)b * HW + (size_t)chunk * 128) * (Cc / 4);

#pragma unroll
    for (int r = 0; r < 16; ++r) {
        const int row = warp * 16 + r;
        const float4* xrow = x4 + (size_t)row * (Cc / 4);
        float p = 0.0f;
#pragma unroll
        for (int k = 0; k < 4; ++k) {
            float4 xv = xrow[lane + 32 * k];
            float4 uv = u4[lane + 32 * k];
            p += xv.x * uv.x + xv.y * uv.y + xv.z * uv.z + xv.w * uv.w;
        }
#pragma unroll
        for (int off = 16; off; off >>= 1)
            p += __shfl_xor_sync(0xffffffffu, p, off);
        if (lane == 0)
            g_dot[b * HW + chunk * 128 + row] = p;
    }
}

// ---------------------------------------------------------------------------
// Kernel 4: per-batch min/max normalize + sigmoid.  grid Bb, block 1024.
// ---------------------------------------------------------------------------
__global__ void k_norm(float* __restrict__ out) {
    __shared__ float smn[32], smx[32];
    const int b = blockIdx.x;
    const int t = threadIdx.x;
    const int warp = t >> 5, lane = t & 31;

    const float v = g_dot[b * HW + t];
    float mn = v, mx = v;
#pragma unroll
    for (int off = 16; off; off >>= 1) {
        mn = fminf(mn, __shfl_xor_sync(0xffffffffu, mn, off));
        mx = fmaxf(mx, __shfl_xor_sync(0xffffffffu, mx, off));
    }
    if (lane == 0) { smn[warp] = mn; smx[warp] = mx; }
    __syncthreads();
    if (warp == 0) {
        mn = smn[lane]; mx = smx[lane];
#pragma unroll
        for (int off = 16; off; off >>= 1) {
            mn = fminf(mn, __shfl_xor_sync(0xffffffffu, mn, off));
            mx = fmaxf(mx, __shfl_xor_sync(0xffffffffu, mx, off));
        }
        if (lane == 0) { smn[0] = mn; smx[0] = mx; }
    }
    __syncthreads();
    mn = smn[0]; mx = smx[0];

    const float r = (v - mn) / (mx - mn);
    const float z = (r - 0.65f) / 0.15f;
    out[b * HW + t] = 1.0f / (1.0f + expf(-z));
}

// ---------------------------------------------------------------------------
extern "C" void kernel_launch(void* const* d_in, const int* in_sizes, int n_in,
                              void* d_out, int out_size) {
    const float* x      = (const float*)d_in[0];
    const float* conv_w = (const float*)d_in[1];
    const float* conv_b = (const float*)d_in[2];
    const float* q_w    = (const float*)d_in[3];
    // d_in[4] = q_b: its contribution is a per-batch constant that cancels in
    // the min/max normalization -> unused.
    const float* k_w    = (const float*)d_in[5];
    const float* k_b    = (const float*)d_in[6];
    float* out = (float*)d_out;

    k_colsum<<<dim3(Bb, NSPLIT), Cc>>>(x);
    k_stage1<<<Bb, Cc>>>(conv_w, conv_b, k_w, k_b);
    k_stage2<<<Bb, Cc>>>(conv_w, q_w);
    k_dot<<<dim3(8, Bb), 256>>>(x);
    k_norm<<<Bb, HW>>>(out);
}

// round 2
// speedup vs baseline: 1.7509x; 1.7509x over previous
#include <cuda_runtime.h>
#include <math.h>

#define Bb     8
#define HW     1024
#define Cc     512
#define C4     (Cc / 4)        // 128 float4 per row
#define NBLK   128
#define NTHR   512
#define NSPLIT 16              // colsum splits per batch (16 blocks/batch)

// ---------------- scratch (__device__ globals; fully rewritten each launch) --
__device__ float4 g_partial4[Bb][NSPLIT][4][C4];   // colsum partials (1 MB)
__device__ float  g_xr[Bb][Cc];
__device__ float  g_ksum[Bb][Cc];
__device__ float  g_wpart[16][Bb][Cc];
__device__ float  g_upart[16][Bb][Cc];
__device__ float  g_dot[Bb][HW];

// ---------------- software grid barrier (sense reversal) ---------------------
__device__ unsigned g_bar_count = 0;
__device__ unsigned g_bar_sense = 0;

__device__ __forceinline__ void grid_barrier(unsigned* s_sense) {
    __syncthreads();
    if (threadIdx.x == 0) {
        __threadfence();                       // publish this block's writes
        unsigned target = *s_sense ^ 1u;
        *s_sense = target;
        unsigned prev = atomicAdd(&g_bar_count, 1u);
        if (prev == NBLK - 1) {
            g_bar_count = 0;                   // reset for next barrier
            __threadfence();
            atomicExch(&g_bar_sense, target);  // release
        } else {
            while (atomicAdd(&g_bar_sense, 0u) != target) __nanosleep(32);
        }
        __threadfence();                       // acquire
    }
    __syncthreads();
}

// ---------------- the fused kernel -------------------------------------------
__global__ void __launch_bounds__(NTHR)
fused_kernel(const float* __restrict__ x,
             const float* __restrict__ conv_w, const float* __restrict__ conv_b,
             const float* __restrict__ q_w,
             const float* __restrict__ k_w,    const float* __restrict__ k_b,
             float* __restrict__ out)
{
    __shared__ __align__(16) float shA[Bb][Cc];   // 16 KB (vectors for all 8 b)
    __shared__ __align__(16) float shB[Cc];       // 2 KB
    __shared__ unsigned s_sense;

    const int g    = blockIdx.x;
    const int t    = threadIdx.x;
    const int warp = t >> 5, lane = t & 31;

    if (t == 0) s_sense = g_bar_sense;  // safe: sense can't flip until all
    __syncthreads();                    // blocks reach barrier 1 (after this)

    // ---- P1: column sums of x (DRAM pass #1). block g: batch g>>4, split g&15.
    // Thread layout: c4 = t&127 (float4 column), rs = t>>7 (row subgroup of 16).
    {
        const int b  = g >> 4, s = g & 15;
        const int c4 = t & 127, rs = t >> 7;
        const float4* base = reinterpret_cast<const float4*>(x)
                           + ((size_t)(b * HW + s * 64 + rs * 16)) * C4 + c4;
        float4 acc = make_float4(0.f, 0.f, 0.f, 0.f);
#pragma unroll
        for (int p = 0; p < 16; ++p) {
            float4 v = base[(size_t)p * C4];
            acc.x += v.x; acc.y += v.y; acc.z += v.z; acc.w += v.w;
        }
        g_partial4[b][s][rs][c4] = acc;
    }
    grid_barrier(&s_sense);

    // ---- P2: Xsum reduce + conv matvec, batched over b. blocks 0..31,
    //          warp per output row (32 blocks x 16 warps = 512 rows).
    if (g < 32) {
        for (int idx = t; idx < Bb * C4; idx += NTHR) {
            const int b = idx >> 7, c4 = idx & 127;
            float4 a = make_float4(0.f, 0.f, 0.f, 0.f);
#pragma unroll
            for (int s = 0; s < NSPLIT; ++s)
#pragma unroll
                for (int rs = 0; rs < 4; ++rs) {
                    float4 v = g_partial4[b][s][rs][c4];
                    a.x += v.x; a.y += v.y; a.z += v.z; a.w += v.w;
                }
            reinterpret_cast<float4*>(shA[b])[c4] = a;
        }
        __syncthreads();

        const int o = g * 16 + warp;
        const float* wrow = conv_w + (size_t)o * Cc;
        float acc[Bb];
#pragma unroll
        for (int b = 0; b < Bb; ++b) acc[b] = 0.f;
#pragma unroll
        for (int k = 0; k < 16; ++k) {
            const int c = lane + 32 * k;
            const float wv = wrow[c];
#pragma unroll
            for (int b = 0; b < Bb; ++b) acc[b] += wv * shA[b][c];
        }
#pragma unroll
        for (int b = 0; b < Bb; ++b)
#pragma unroll
            for (int off = 16; off; off >>= 1)
                acc[b] += __shfl_xor_sync(0xffffffffu, acc[b], off);
        if (lane == 0) {
            const float cb = (float)HW * conv_b[o];
#pragma unroll
            for (int b = 0; b < Bb; ++b)
                g_xr[b][o] = acc[b] + cb + shA[b][o];
        }
    }
    grid_barrier(&s_sense);

    // ---- P3: Ksum = k_w @ XRsum + HW*k_b, batched. blocks 0..31.
    if (g < 32) {
        for (int idx = t; idx < Bb * Cc; idx += NTHR)
            shA[idx >> 9][idx & 511] = g_xr[idx >> 9][idx & 511];
        __syncthreads();

        const int o = g * 16 + warp;
        const float* wrow = k_w + (size_t)o * Cc;
        float acc[Bb];
#pragma unroll
        for (int b = 0; b < Bb; ++b) acc[b] = 0.f;
#pragma unroll
        for (int k = 0; k < 16; ++k) {
            const int c = lane + 32 * k;
            const float wv = wrow[c];
#pragma unroll
            for (int b = 0; b < Bb; ++b) acc[b] += wv * shA[b][c];
        }
#pragma unroll
        for (int b = 0; b < Bb; ++b)
#pragma unroll
            for (int off = 16; off; off >>= 1)
                acc[b] += __shfl_xor_sync(0xffffffffu, acc[b], off);
        if (lane == 0) {
            const float kb = (float)HW * k_b[o];
#pragma unroll
            for (int b = 0; b < Bb; ++b)
                g_ksum[b][o] = acc[b] + kb;
        }
    }
    grid_barrier(&s_sense);

    // ---- P4: v_b = KsumAll - Ksum[b];  partial w[b] = q_w^T v_b over o-chunk.
    //          blocks 0..15, chunk j=g covers o in [32j, 32j+32).
    if (g < 16) {
        float tot = 0.f;
#pragma unroll
        for (int b = 0; b < Bb; ++b) tot += g_ksum[b][t];
        shB[t] = tot;
        __syncthreads();
        for (int idx = t; idx < Bb * Cc; idx += NTHR) {
            const int b = idx >> 9, c = idx & 511;
            shA[b][c] = shB[c] - g_ksum[b][c];
        }
        __syncthreads();

        float acc[Bb];
#pragma unroll
        for (int b = 0; b < Bb; ++b) acc[b] = 0.f;
#pragma unroll
        for (int oo = 0; oo < 32; ++oo) {
            const int o = g * 32 + oo;
            const float wv = q_w[(size_t)o * Cc + t];   // coalesced over t
#pragma unroll
            for (int b = 0; b < Bb; ++b) acc[b] += wv * shA[b][o];
        }
#pragma unroll
        for (int b = 0; b < Bb; ++b) g_wpart[g][b][t] = acc[b];
    }
    grid_barrier(&s_sense);

    // ---- P5: reduce w; partial u[b] = conv_w^T w_b over o-chunk (+w term, j=0).
    if (g < 16) {
        for (int idx = t; idx < Bb * Cc; idx += NTHR) {
            const int b = idx >> 9, c = idx & 511;
            float a = 0.f;
#pragma unroll
            for (int j = 0; j < 16; ++j) a += g_wpart[j][b][c];
            shA[b][c] = a;
        }
        __syncthreads();

        float acc[Bb];
#pragma unroll
        for (int b = 0; b < Bb; ++b) acc[b] = 0.f;
#pragma unroll
        for (int oo = 0; oo < 32; ++oo) {
            const int o = g * 32 + oo;
            const float wv = conv_w[(size_t)o * Cc + t];
#pragma unroll
            for (int b = 0; b < Bb; ++b) acc[b] += wv * shA[b][o];
        }
        if (g == 0) {
#pragma unroll
            for (int b = 0; b < Bb; ++b) acc[b] += shA[b][t];  // +w[b][c]
        }
#pragma unroll
        for (int b = 0; b < Bb; ++b) g_upart[g][b][t] = acc[b];
    }
    grid_barrier(&s_sense);

    // ---- P6: dot[b,i] = x[b,i] . u_b  (x now L2-resident). all 128 blocks,
    //          block g: batch g>>4, rows (g&15)*64 .. +64; warp -> 4 rows.
    {
        const int b = g >> 4, rowbase = (g & 15) * 64;
        float a = 0.f;
#pragma unroll
        for (int j = 0; j < 16; ++j) a += g_upart[j][b][t];
        shB[t] = a;
        __syncthreads();

        const float4* u4 = reinterpret_cast<const float4*>(shB);
#pragma unroll
        for (int r = 0; r < 4; ++r) {
            const int row = rowbase + warp * 4 + r;
            const float4* xr4 = reinterpret_cast<const float4*>(x)
                              + ((size_t)(b * HW + row)) * C4;
            float p = 0.f;
#pragma unroll
            for (int k = 0; k < 4; ++k) {
                const float4 xv = xr4[lane + 32 * k];
                const float4 uv = u4[lane + 32 * k];
                p += xv.x * uv.x + xv.y * uv.y + xv.z * uv.z + xv.w * uv.w;
            }
#pragma unroll
            for (int off = 16; off; off >>= 1)
                p += __shfl_xor_sync(0xffffffffu, p, off);
            if (lane == 0) g_dot[b][row] = p;
        }
    }
    grid_barrier(&s_sense);

    // ---- P7: per-batch min/max normalize + sigmoid. blocks 0..7.
    if (g < Bb) {
        __shared__ float smn[16], smx[16];
        const int b = g;
        const float v0 = g_dot[b][t];
        const float v1 = g_dot[b][t + 512];
        float mn = fminf(v0, v1), mx = fmaxf(v0, v1);
#pragma unroll
        for (int off = 16; off; off >>= 1) {
            mn = fminf(mn, __shfl_xor_sync(0xffffffffu, mn, off));
            mx = fmaxf(mx, __shfl_xor_sync(0xffffffffu, mx, off));
        }
        if (lane == 0) { smn[warp] = mn; smx[warp] = mx; }
        __syncthreads();
        if (warp == 0) {
            mn = smn[lane & 15]; mx = smx[lane & 15];
#pragma unroll
            for (int off = 8; off; off >>= 1) {
                mn = fminf(mn, __shfl_xor_sync(0xffffffffu, mn, off));
                mx = fmaxf(mx, __shfl_xor_sync(0xffffffffu, mx, off));
            }
            if (lane == 0) { smn[0] = mn; smx[0] = mx; }
        }
        __syncthreads();
        mn = smn[0]; mx = smx[0];
        const float inv = 1.0f / (mx - mn);
        {
            const float r0 = (v0 - mn) * inv;
            const float z0 = (r0 - 0.65f) / 0.15f;
            out[b * HW + t] = 1.0f / (1.0f + __expf(-z0));
            const float r1 = (v1 - mn) * inv;
            const float z1 = (r1 - 0.65f) / 0.15f;
            out[b * HW + t + 512] = 1.0f / (1.0f + __expf(-z1));
        }
    }
}

// ---------------------------------------------------------------------------
extern "C" void kernel_launch(void* const* d_in, const int* in_sizes, int n_in,
                              void* d_out, int out_size) {
    const float* x      = (const float*)d_in[0];
    const float* conv_w = (const float*)d_in[1];
    const float* conv_b = (const float*)d_in[2];
    const float* q_w    = (const float*)d_in[3];
    // d_in[4] = q_b: per-batch constant, cancels in min/max normalization.
    const float* k_w    = (const float*)d_in[5];
    const float* k_b    = (const float*)d_in[6];
    float* out = (float*)d_out;

    fused_kernel<<<NBLK, NTHR>>>(x, conv_w, conv_b, q_w, k_w, k_b, out);
}

// round 3
// speedup vs baseline: 2.2801x; 1.3022x over previous
#include <cuda_runtime.h>
#include <math.h>

#define Bb     8
#define HW     1024
#define Cc     512
#define C4     128            // float4 per row
#define NBLK   128
#define NTHR   512
#define NSPLIT 16
#define TILE_BYTES (64 * Cc * sizeof(float))   // 128 KB x-tile per block

// -------- scratch (__device__ globals; counters reset at end of each launch) --
__device__ __align__(16) float4 g_partial[Bb][NSPLIT][C4]; // per-(b,split) colsum
__device__ __align__(16) float4 g_xsum4[Bb][C4];
__device__ __align__(16) float  g_xr[Bb][Cc];
__device__ __align__(16) float  g_ksum[Bb][Cc];
__device__ __align__(16) float  g_wpart[16][Bb][Cc];
__device__ __align__(16) float  g_upart[16][Bb][Cc];
__device__ __align__(16) float  g_u[Bb][Cc];
__device__ float    g_dot[Bb][HW];
__device__ unsigned g_cnt[9];
__device__ unsigned g_uflag;

// monotonic >= barriers: arrival via atomicAdd, wait via volatile-load spin.
#define ARRIVE(i)                                                     \
    do { __syncthreads();                                             \
         if (t == 0) { __threadfence(); atomicAdd(&g_cnt[i], 1u); }   \
    } while (0)
#define WAITGE(i, tgt)                                                \
    do { if (t == 0) {                                                \
             while (*(volatile unsigned*)&g_cnt[i] < (unsigned)(tgt)) {} \
             __threadfence();                                         \
         }                                                            \
         __syncthreads();                                             \
    } while (0)

__global__ void __launch_bounds__(NTHR)
fused_kernel(const float* __restrict__ x,
             const float* __restrict__ conv_w, const float* __restrict__ conv_b,
             const float* __restrict__ q_w,
             const float* __restrict__ k_w,    const float* __restrict__ k_b,
             float* __restrict__ out)
{
    extern __shared__ float4 tile4[];               // 64 rows x 128 float4
    __shared__ __align__(16) float shA[Bb][Cc];     // 16 KB
    __shared__ __align__(16) float shB[Cc];         // 2 KB

    const int g    = blockIdx.x;
    const int t    = threadIdx.x;
    const int warp = t >> 5, lane = t & 31;
    const int b_own = g >> 4, s_own = g & 15;       // this block's x tile

    // ---- P1: load own 64-row tile into smem; column partial sums -> global.
    {
        const int c4 = t & 127, rs = t >> 7;        // rs: 4 groups of 16 rows
        const float4* base = reinterpret_cast<const float4*>(x)
                           + ((size_t)(b_own * HW + s_own * 64 + rs * 16)) * C4 + c4;
        float4 acc = make_float4(0.f, 0.f, 0.f, 0.f);
#pragma unroll
        for (int p = 0; p < 16; ++p) {
            float4 v = base[(size_t)p * C4];
            tile4[(rs * 16 + p) * C4 + c4] = v;
            acc.x += v.x; acc.y += v.y; acc.z += v.z; acc.w += v.w;
        }
        float4* shP = reinterpret_cast<float4*>(shA);  // reuse shA: [4][128]
        shP[rs * C4 + c4] = acc;
        __syncthreads();
        if (t < C4) {
            float4 a = shP[t], p1 = shP[C4 + t], p2 = shP[2 * C4 + t], p3 = shP[3 * C4 + t];
            a.x += p1.x + p2.x + p3.x;  a.y += p1.y + p2.y + p3.y;
            a.z += p1.z + p2.z + p3.z;  a.w += p1.w + p2.w + p3.w;
            g_partial[b_own][s_own][t] = a;
        }
    }
    ARRIVE(0);

    // ======================= mid-chain: 32 worker blocks ======================
    if (g < 32) {
        WAITGE(0, NBLK);

        // ---- P2a: reduce partials over splits -> g_xsum4. 1024 float4 outputs.
        {
            const int o  = g * 32 + (t >> 4);   // output float4 index 0..1023
            const int s  = t & 15;
            const int bb = o >> 7, c4 = o & 127;
            float4 v = g_partial[bb][s][c4];
#pragma unroll
            for (int off = 8; off; off >>= 1) {
                v.x += __shfl_xor_sync(0xffffffffu, v.x, off);
                v.y += __shfl_xor_sync(0xffffffffu, v.y, off);
                v.z += __shfl_xor_sync(0xffffffffu, v.z, off);
                v.w += __shfl_xor_sync(0xffffffffu, v.w, off);
            }
            if (s == 0) g_xsum4[bb][c4] = v;
        }
        ARRIVE(1); WAITGE(1, 32);

        // ---- P2b: xr = conv_w @ Xsum + HW*conv_b + Xsum (batched over b).
        {
            float4* shA4 = reinterpret_cast<float4*>(shA);
            const float4* gx4 = reinterpret_cast<const float4*>(g_xsum4);
#pragma unroll
            for (int idx = t; idx < Bb * C4; idx += NTHR) shA4[idx] = gx4[idx];
            __syncthreads();

            const int o = g * 16 + warp;
            const float* wrow = conv_w + (size_t)o * Cc;
            float acc[Bb];
#pragma unroll
            for (int b = 0; b < Bb; ++b) acc[b] = 0.f;
#pragma unroll
            for (int k = 0; k < 16; ++k) {
                const int c = lane + 32 * k;
                const float wv = wrow[c];
#pragma unroll
                for (int b = 0; b < Bb; ++b) acc[b] += wv * shA[b][c];
            }
#pragma unroll
            for (int b = 0; b < Bb; ++b)
#pragma unroll
                for (int off = 16; off; off >>= 1)
                    acc[b] += __shfl_xor_sync(0xffffffffu, acc[b], off);
            if (lane == 0) {
                const float cb = (float)HW * conv_b[o];
#pragma unroll
                for (int b = 0; b < Bb; ++b)
                    g_xr[b][o] = acc[b] + cb + shA[b][o];
            }
        }
        ARRIVE(2); WAITGE(2, 32);

        // ---- P3: Ksum = k_w @ xr + HW*k_b.
        {
            float4* shA4 = reinterpret_cast<float4*>(shA);
            const float4* gxr4 = reinterpret_cast<const float4*>(g_xr);
#pragma unroll
            for (int idx = t; idx < Bb * C4; idx += NTHR) shA4[idx] = gxr4[idx];
            __syncthreads();

            const int o = g * 16 + warp;
            const float* wrow = k_w + (size_t)o * Cc;
            float acc[Bb];
#pragma unroll
            for (int b = 0; b < Bb; ++b) acc[b] = 0.f;
#pragma unroll
            for (int k = 0; k < 16; ++k) {
                const int c = lane + 32 * k;
                const float wv = wrow[c];
#pragma unroll
                for (int b = 0; b < Bb; ++b) acc[b] += wv * shA[b][c];
            }
#pragma unroll
            for (int b = 0; b < Bb; ++b)
#pragma unroll
                for (int off = 16; off; off >>= 1)
                    acc[b] += __shfl_xor_sync(0xffffffffu, acc[b], off);
            if (lane == 0) {
                const float kb = (float)HW * k_b[o];
#pragma unroll
                for (int b = 0; b < Bb; ++b)
                    g_ksum[b][o] = acc[b] + kb;
            }
        }
        ARRIVE(3); WAITGE(3, 32);

        // ---- P4 (g<16): v_b = KsumAll - Ksum_b; partial w = q_w^T v over o-chunk.
        if (g < 16) {
            float tot = 0.f;
#pragma unroll
            for (int b = 0; b < Bb; ++b) tot += g_ksum[b][t];
            shB[t] = tot;
            __syncthreads();
#pragma unroll
            for (int idx = t; idx < Bb * Cc; idx += NTHR) {
                const int b = idx >> 9, c = idx & 511;
                shA[b][c] = shB[c] - g_ksum[b][c];
            }
            __syncthreads();

            float acc[Bb];
#pragma unroll
            for (int b = 0; b < Bb; ++b) acc[b] = 0.f;
#pragma unroll
            for (int oo = 0; oo < 32; ++oo) {
                const int o = g * 32 + oo;
                const float wv = q_w[(size_t)o * Cc + t];
#pragma unroll
                for (int b = 0; b < Bb; ++b) acc[b] += wv * shA[b][o];
            }
#pragma unroll
            for (int b = 0; b < Bb; ++b) g_wpart[g][b][t] = acc[b];
        }
        ARRIVE(4); WAITGE(4, 32);

        // ---- P5 (g<16): reduce w; partial u = conv_w^T w over o-chunk (+w, g==0).
        if (g < 16) {
#pragma unroll
            for (int idx = t; idx < Bb * Cc; idx += NTHR) {
                const int b = idx >> 9, c = idx & 511;
                float a = 0.f;
#pragma unroll
                for (int j = 0; j < 16; ++j) a += g_wpart[j][b][c];
                shA[b][c] = a;
            }
            __syncthreads();

            float acc[Bb];
#pragma unroll
            for (int b = 0; b < Bb; ++b) acc[b] = 0.f;
#pragma unroll
            for (int oo = 0; oo < 32; ++oo) {
                const int o = g * 32 + oo;
                const float wv = conv_w[(size_t)o * Cc + t];
#pragma unroll
                for (int b = 0; b < Bb; ++b) acc[b] += wv * shA[b][o];
            }
            if (g == 0) {
#pragma unroll
                for (int b = 0; b < Bb; ++b) acc[b] += shA[b][t];
            }
#pragma unroll
            for (int b = 0; b < Bb; ++b) g_upart[g][b][t] = acc[b];
        }
        ARRIVE(5); WAITGE(5, 32);

        // ---- P5b (g<8): reduce u-partials -> g_u. last arriver publishes u_ready.
        if (g < 8) {
            const int idx = g * NTHR + t;          // covers all 8*512 elements
            const int b = idx >> 9, c = idx & 511;
            float a = 0.f;
#pragma unroll
            for (int j = 0; j < 16; ++j) a += g_upart[j][b][c];
            g_u[b][c] = a;
        }
        __syncthreads();
        if (t == 0) {
            __threadfence();
            unsigned prev = atomicAdd(&g_cnt[6], 1u);
            if (prev == 31u) atomicExch(&g_uflag, 1u);
        }
    }

    // ======================= all 128 blocks: wait for u ======================
    if (t == 0) {
        while (*(volatile unsigned*)&g_uflag == 0u) {}
        __threadfence();
    }
    __syncthreads();

    // ---- P6: dot over own smem tile.
    {
#pragma unroll
        for (int idx = t; idx < Cc; idx += NTHR) shB[idx] = g_u[b_own][idx];
        __syncthreads();

        const float4* u4 = reinterpret_cast<const float4*>(shB);
#pragma unroll
        for (int r = 0; r < 4; ++r) {
            const int row = warp * 4 + r;
            float p = 0.f;
#pragma unroll
            for (int k = 0; k < 4; ++k) {
                const float4 xv = tile4[row * C4 + lane + 32 * k];
                const float4 uv = u4[lane + 32 * k];
                p += xv.x * uv.x + xv.y * uv.y + xv.z * uv.z + xv.w * uv.w;
            }
#pragma unroll
            for (int off = 16; off; off >>= 1)
                p += __shfl_xor_sync(0xffffffffu, p, off);
            if (lane == 0) g_dot[b_own][s_own * 64 + row] = p;
        }
    }
    ARRIVE(7);

    // ---- P7 (g<8): per-batch min/max normalize + sigmoid; last block resets.
    if (g < Bb) {
        WAITGE(7, NBLK);
        __shared__ float smn[16], smx[16];
        const int b = g;
        const float v0 = g_dot[b][t];
        const float v1 = g_dot[b][t + 512];
        float mn = fminf(v0, v1), mx = fmaxf(v0, v1);
#pragma unroll
        for (int off = 16; off; off >>= 1) {
            mn = fminf(mn, __shfl_xor_sync(0xffffffffu, mn, off));
            mx = fmaxf(mx, __shfl_xor_sync(0xffffffffu, mx, off));
        }
        if (lane == 0) { smn[warp] = mn; smx[warp] = mx; }
        __syncthreads();
        if (warp == 0) {
            mn = smn[lane & 15]; mx = smx[lane & 15];
#pragma unroll
            for (int off = 8; off; off >>= 1) {
                mn = fminf(mn, __shfl_xor_sync(0xffffffffu, mn, off));
                mx = fmaxf(mx, __shfl_xor_sync(0xffffffffu, mx, off));
            }
            if (lane == 0) { smn[0] = mn; smx[0] = mx; }
        }
        __syncthreads();
        mn = smn[0]; mx = smx[0];
        const float inv = 1.0f / (mx - mn);
        {
            const float z0 = ((v0 - mn) * inv - 0.65f) / 0.15f;
            out[b * HW + t] = 1.0f / (1.0f + __expf(-z0));
            const float z1 = ((v1 - mn) * inv - 0.65f) / 0.15f;
            out[b * HW + t + 512] = 1.0f / (1.0f + __expf(-z1));
        }
        // final arrival; the very last block resets all sync state for replay.
        __syncthreads();
        if (t == 0) {
            unsigned prev = atomicAdd(&g_cnt[8], 1u);
            if (prev == Bb - 1u) {
#pragma unroll
                for (int i = 0; i < 9; ++i) g_cnt[i] = 0u;
                g_uflag = 0u;
                __threadfence();
            }
        }
    }
}

// ---------------------------------------------------------------------------
extern "C" void kernel_launch(void* const* d_in, const int* in_sizes, int n_in,
                              void* d_out, int out_size) {
    const float* x      = (const float*)d_in[0];
    const float* conv_w = (const float*)d_in[1];
    const float* conv_b = (const float*)d_in[2];
    const float* q_w    = (const float*)d_in[3];
    // d_in[4] = q_b: per-batch constant, cancels in min/max normalization.
    const float* k_w    = (const float*)d_in[5];
    const float* k_b    = (const float*)d_in[6];
    float* out = (float*)d_out;

    cudaFuncSetAttribute(fused_kernel,
                         cudaFuncAttributeMaxDynamicSharedMemorySize,
                         (int)TILE_BYTES);
    fused_kernel<<<NBLK, NTHR, TILE_BYTES>>>(x, conv_w, conv_b, q_w, k_w, k_b, out);
}

// round 4
// speedup vs baseline: 2.4273x; 1.0645x over previous
#include <cuda_runtime.h>
#include <math.h>

#define Bb     8
#define HW     1024
#define Cc     512
#define C4     128
#define NBLK   128
#define NTHR   512
#define NSPLIT 16
#define DYN_BYTES (64 * Cc * 4 + 64 * 1024)   // 128KB x-tile + 64KB weight buf

// -------- scratch (__device__ globals; sync state reset at end of launch) ----
__device__ __align__(16) float4 g_partial[Bb][NSPLIT][C4];
__device__ __align__(16) float4 g_xsum4[Bb][C4];
__device__ __align__(16) float  g_xr[Bb][Cc];
__device__ __align__(16) float  g_ksum[Bb][Cc];
__device__ __align__(16) float  g_wpart[16][Bb][Cc];
__device__ __align__(16) float  g_w[Bb][Cc];
__device__ __align__(16) float  g_upart[16][Bb][Cc];
__device__ unsigned g_cnt[9];
__device__ unsigned g_mnk[Bb] = {0xFFFFFFFFu,0xFFFFFFFFu,0xFFFFFFFFu,0xFFFFFFFFu,
                                 0xFFFFFFFFu,0xFFFFFFFFu,0xFFFFFFFFu,0xFFFFFFFFu};
__device__ unsigned g_mxk[Bb] = {0,0,0,0,0,0,0,0};

#define ARRIVE(i)                                                     \
    do { __syncthreads();                                             \
         if (t == 0) { __threadfence(); atomicAdd(&g_cnt[i], 1u); }   \
    } while (0)
#define WAITGE(i, tgt)                                                \
    do { if (t == 0) {                                                \
             while (*(volatile unsigned*)&g_cnt[i] < (unsigned)(tgt)) {} \
             __threadfence();                                         \
         }                                                            \
         __syncthreads();                                             \
    } while (0)

__device__ __forceinline__ unsigned enc(float f) {
    unsigned u = __float_as_uint(f);
    return (u & 0x80000000u) ? ~u : (u | 0x80000000u);
}
__device__ __forceinline__ float dec(unsigned k) {
    return (k & 0x80000000u) ? __uint_as_float(k ^ 0x80000000u)
                             : __uint_as_float(~k);
}

__global__ void __launch_bounds__(NTHR)
fused_kernel(const float* __restrict__ x,
             const float* __restrict__ conv_w, const float* __restrict__ conv_b,
             const float* __restrict__ q_w,
             const float* __restrict__ k_w,    const float* __restrict__ k_b,
             float* __restrict__ out)
{
    extern __shared__ float4 dyn4[];
    float4* tile4 = dyn4;                            // 8192 float4 (128 KB)
    float*  wbuf  = reinterpret_cast<float*>(dyn4 + 8192);   // 16384 f (64 KB)
    __shared__ __align__(16) float shA[Bb][Cc];      // 16 KB
    __shared__ __align__(16) float shB[Cc];          // 2 KB
    __shared__ float sdot[64];

    const int g    = blockIdx.x;
    const int t    = threadIdx.x;
    const int warp = t >> 5, lane = t & 31;
    const int b_own = g >> 4, s_own = g & 15;

    // ================= P1: x tile -> smem (+colsum) & weight prefetch ========
    {
        const int c4 = t & 127, rs = t >> 7;
        const float4* base = reinterpret_cast<const float4*>(x)
                           + ((size_t)(b_own * HW + s_own * 64 + rs * 16)) * C4 + c4;
        float4 acc = make_float4(0.f, 0.f, 0.f, 0.f);
#pragma unroll
        for (int p = 0; p < 16; ++p) {
            float4 v = base[(size_t)p * C4];
            tile4[(rs * 16 + p) * C4 + c4] = v;
            acc.x += v.x; acc.y += v.y; acc.z += v.z; acc.w += v.w;
        }
        float4* shP = reinterpret_cast<float4*>(shA);
        shP[rs * C4 + c4] = acc;

        // weight prefetch (overlaps with x loads still in flight)
        float4* wb4 = reinterpret_cast<float4*>(wbuf);
        if (g >= 32 && g < 64) {            // A: conv_w rows [(g-32)*16, +16)
            const float4* src = reinterpret_cast<const float4*>(conv_w) + (g - 32) * 2048;
#pragma unroll
            for (int i = 0; i < 4; ++i) wb4[t + i * NTHR] = src[t + i * NTHR];
        } else if (g >= 64 && g < 96) {     // B: k_w rows [(g-64)*16, +16)
            const float4* src = reinterpret_cast<const float4*>(k_w) + (g - 64) * 2048;
#pragma unroll
            for (int i = 0; i < 4; ++i) wb4[t + i * NTHR] = src[t + i * NTHR];
        } else if (g < 16) {                // C: q_w rows [g*32, +32)
            const float4* src = reinterpret_cast<const float4*>(q_w) + g * 4096;
#pragma unroll
            for (int i = 0; i < 8; ++i) wb4[t + i * NTHR] = src[t + i * NTHR];
        } else if (g >= 16 && g < 32) {     // D: conv_w rows [(g-16)*32, +32)
            const float4* src = reinterpret_cast<const float4*>(conv_w) + (g - 16) * 4096;
#pragma unroll
            for (int i = 0; i < 8; ++i) wb4[t + i * NTHR] = src[t + i * NTHR];
        }
        __syncthreads();
        if (t < C4) {
            float4 a = shP[t], p1 = shP[C4 + t], p2 = shP[2 * C4 + t], p3 = shP[3 * C4 + t];
            a.x += p1.x + p2.x + p3.x;  a.y += p1.y + p2.y + p3.y;
            a.z += p1.z + p2.z + p3.z;  a.w += p1.w + p2.w + p3.w;
            g_partial[b_own][s_own][t] = a;
        }
    }
    ARRIVE(0);

    // ================= group A (blocks 32..63): Xsum + conv matvec ===========
    if (g >= 32 && g < 64) {
        const int a = g - 32;
        WAITGE(0, NBLK);
        // P2a: split Xsum reduce: this block does float4 outputs [a*32, a*32+32)
        {
            const int o = a * 32 + (t >> 4), s = t & 15;
            const int bb = o >> 7, c4 = o & 127;
            float4 v = g_partial[bb][s][c4];
#pragma unroll
            for (int off = 8; off; off >>= 1) {
                v.x += __shfl_xor_sync(0xffffffffu, v.x, off);
                v.y += __shfl_xor_sync(0xffffffffu, v.y, off);
                v.z += __shfl_xor_sync(0xffffffffu, v.z, off);
                v.w += __shfl_xor_sync(0xffffffffu, v.w, off);
            }
            if (s == 0) g_xsum4[bb][c4] = v;
        }
        ARRIVE(1); WAITGE(1, 32);
        // P2b: xr = conv_w @ Xsum + HW*conv_b + Xsum (weights from smem)
        {
            float4* shA4 = reinterpret_cast<float4*>(shA);
            const float4* gx4 = reinterpret_cast<const float4*>(g_xsum4);
#pragma unroll
            for (int i = 0; i < 2; ++i) shA4[t + i * NTHR] = gx4[t + i * NTHR];
            __syncthreads();

            const int o = a * 16 + warp;
            float acc[Bb];
#pragma unroll
            for (int b = 0; b < Bb; ++b) acc[b] = 0.f;
#pragma unroll
            for (int k = 0; k < 16; ++k) {
                const int c = lane + 32 * k;
                const float wv = wbuf[warp * Cc + c];
#pragma unroll
                for (int b = 0; b < Bb; ++b) acc[b] += wv * shA[b][c];
            }
#pragma unroll
            for (int b = 0; b < Bb; ++b)
#pragma unroll
                for (int off = 16; off; off >>= 1)
                    acc[b] += __shfl_xor_sync(0xffffffffu, acc[b], off);
            if (lane == 0) {
                const float cb = (float)HW * conv_b[o];
#pragma unroll
                for (int b = 0; b < Bb; ++b)
                    g_xr[b][o] = acc[b] + cb + shA[b][o];
            }
        }
        ARRIVE(2);
    }

    // ================= group B (blocks 64..95): Ksum matvec ==================
    if (g >= 64 && g < 96) {
        const int bbk = g - 64;
        WAITGE(2, 32);
        {
            float4* shA4 = reinterpret_cast<float4*>(shA);
            const float4* gxr4 = reinterpret_cast<const float4*>(g_xr);
#pragma unroll
            for (int i = 0; i < 2; ++i) shA4[t + i * NTHR] = gxr4[t + i * NTHR];
            __syncthreads();

            const int o = bbk * 16 + warp;
            float acc[Bb];
#pragma unroll
            for (int b = 0; b < Bb; ++b) acc[b] = 0.f;
#pragma unroll
            for (int k = 0; k < 16; ++k) {
                const int c = lane + 32 * k;
                const float wv = wbuf[warp * Cc + c];
#pragma unroll
                for (int b = 0; b < Bb; ++b) acc[b] += wv * shA[b][c];
            }
#pragma unroll
            for (int b = 0; b < Bb; ++b)
#pragma unroll
                for (int off = 16; off; off >>= 1)
                    acc[b] += __shfl_xor_sync(0xffffffffu, acc[b], off);
            if (lane == 0) {
                const float kb = (float)HW * k_b[o];
#pragma unroll
                for (int b = 0; b < Bb; ++b)
                    g_ksum[b][o] = acc[b] + kb;
            }
        }
        ARRIVE(3);
    }

    // ================= group C (blocks 0..15): w partial =====================
    if (g < 16) {
        WAITGE(3, 32);
        float tot = 0.f;
#pragma unroll
        for (int b = 0; b < Bb; ++b) tot += g_ksum[b][t];
        shB[t] = tot;
        __syncthreads();
#pragma unroll
        for (int i = 0; i < Bb; ++i) {
            const int idx = t + i * NTHR;
            const int b = idx >> 9, c = idx & 511;
            shA[b][c] = shB[c] - g_ksum[b][c];
        }
        __syncthreads();

        float acc[Bb];
#pragma unroll
        for (int b = 0; b < Bb; ++b) acc[b] = 0.f;
#pragma unroll
        for (int oo = 0; oo < 32; ++oo) {
            const int o = g * 32 + oo;
            const float wv = wbuf[oo * Cc + t];
#pragma unroll
            for (int b = 0; b < Bb; ++b) acc[b] += wv * shA[b][o];
        }
#pragma unroll
        for (int b = 0; b < Bb; ++b) g_wpart[g][b][t] = acc[b];
        ARRIVE(4);
    }

    // ================= group D (blocks 16..31): w reduce + u partial =========
    if (g >= 16 && g < 32) {
        const int j = g - 16;
        WAITGE(4, 16);
        // split w reduce: this block handles elements [j*256, j*256+256)
        if (t < 256) {
            const int idx = j * 256 + t;
            const int b = idx >> 9, c = idx & 511;
            float a = 0.f;
#pragma unroll
            for (int jj = 0; jj < 16; ++jj) a += g_wpart[jj][b][c];
            g_w[b][c] = a;
        }
        ARRIVE(5); WAITGE(5, 16);
        {
            float4* shA4 = reinterpret_cast<float4*>(shA);
            const float4* gw4 = reinterpret_cast<const float4*>(g_w);
#pragma unroll
            for (int i = 0; i < 2; ++i) shA4[t + i * NTHR] = gw4[t + i * NTHR];
            __syncthreads();

            float acc[Bb];
#pragma unroll
            for (int b = 0; b < Bb; ++b) acc[b] = 0.f;
#pragma unroll
            for (int oo = 0; oo < 32; ++oo) {
                const int o = j * 32 + oo;
                const float wv = wbuf[oo * Cc + t];
#pragma unroll
                for (int b = 0; b < Bb; ++b) acc[b] += wv * shA[b][o];
            }
            if (j == 0) {
#pragma unroll
                for (int b = 0; b < Bb; ++b) acc[b] += shA[b][t];   // +w term
            }
#pragma unroll
            for (int b = 0; b < Bb; ++b) g_upart[j][b][t] = acc[b];
        }
        ARRIVE(6);
    }

    // ================= all blocks: P6 dot + distributed epilogue =============
    WAITGE(6, 16);
    {
        float a = 0.f;
#pragma unroll
        for (int jj = 0; jj < 16; ++jj) a += g_upart[jj][b_own][t];
        shB[t] = a;
        __syncthreads();

        const float4* u4 = reinterpret_cast<const float4*>(shB);
#pragma unroll
        for (int r = 0; r < 4; ++r) {
            const int row = warp * 4 + r;
            float p = 0.f;
#pragma unroll
            for (int k = 0; k < 4; ++k) {
                const float4 xv = tile4[row * C4 + lane + 32 * k];
                const float4 uv = u4[lane + 32 * k];
                p += xv.x * uv.x + xv.y * uv.y + xv.z * uv.z + xv.w * uv.w;
            }
#pragma unroll
            for (int off = 16; off; off >>= 1)
                p += __shfl_xor_sync(0xffffffffu, p, off);
            if (lane == 0) sdot[row] = p;
        }
    }
    __syncthreads();
    // block min/max -> global atomics (encoded monotonic uint)
    if (warp == 0) {
        float v0 = sdot[lane], v1 = sdot[lane + 32];
        float mn = fminf(v0, v1), mx = fmaxf(v0, v1);
#pragma unroll
        for (int off = 16; off; off >>= 1) {
            mn = fminf(mn, __shfl_xor_sync(0xffffffffu, mn, off));
            mx = fmaxf(mx, __shfl_xor_sync(0xffffffffu, mx, off));
        }
        if (lane == 0) {
            atomicMin(&g_mnk[b_own], enc(mn));
            atomicMax(&g_mxk[b_own], enc(mx));
        }
    }
    ARRIVE(7); WAITGE(7, NBLK);

    if (t < 64) {
        const float mn = dec(g_mnk[b_own]);
        const float mx = dec(g_mxk[b_own]);
        const float inv = 1.0f / (mx - mn);
        const float z = ((sdot[t] - mn) * inv - 0.65f) / 0.15f;
        out[b_own * HW + s_own * 64 + t] = 1.0f / (1.0f + __expf(-z));
    }

    // final: reset sync state for next graph replay
    ARRIVE(8);
    if (g == 0 && t == 0) {
        while (*(volatile unsigned*)&g_cnt[8] < (unsigned)NBLK) {}
#pragma unroll
        for (int i = 0; i < 9; ++i) g_cnt[i] = 0u;
#pragma unroll
        for (int b = 0; b < Bb; ++b) { g_mnk[b] = 0xFFFFFFFFu; g_mxk[b] = 0u; }
        __threadfence();
    }
}

// ---------------------------------------------------------------------------
extern "C" void kernel_launch(void* const* d_in, const int* in_sizes, int n_in,
                              void* d_out, int out_size) {
    const float* x      = (const float*)d_in[0];
    const float* conv_w = (const float*)d_in[1];
    const float* conv_b = (const float*)d_in[2];
    const float* q_w    = (const float*)d_in[3];
    // d_in[4] = q_b: per-batch constant, cancels in min/max normalization.
    const float* k_w    = (const float*)d_in[5];
    const float* k_b    = (const float*)d_in[6];
    float* out = (float*)d_out;

    cudaFuncSetAttribute(fused_kernel,
                         cudaFuncAttributeMaxDynamicSharedMemorySize,
                         DYN_BYTES);
    fused_kernel<<<NBLK, NTHR, DYN_BYTES>>>(x, conv_w, conv_b, q_w, k_w, k_b, out);
}

// round 5
// speedup vs baseline: 2.6410x; 1.0881x over previous
#include <cuda_runtime.h>

#define Bb   8
#define HW   1024
#define Cc   512
#define C4   128
#define NBLK 128
#define NTHR 512
#define DYN_BYTES (64 * 1024 + 32 * 1024)   // wbuf (64KB) + psum (32KB)

// ---------------- sync state: one counter per 128-B line ---------------------
struct alignas(128) Line { unsigned v; unsigned pad[31]; };
__device__ Line cnt0[8];    // P1 arrivals, per batch (16 each)
__device__ Line cnt1[4];    // P2a arrivals (32 total, 8/line)
__device__ Line cnt2[4];    // P2b arrivals (32)
__device__ Line cnt3[4];    // P3 arrivals (32)
__device__ Line cnt4[2];    // P4 arrivals (16, 8/line)
__device__ Line cnt6[1];    // P5 arrivals (16)
__device__ Line cnt7[8];    // epilogue arrivals, per batch (16 each)
__device__ Line cnt8[16];   // final ack (8/line)
__device__ unsigned g_mnk[Bb] = {0xFFFFFFFFu,0xFFFFFFFFu,0xFFFFFFFFu,0xFFFFFFFFu,
                                 0xFFFFFFFFu,0xFFFFFFFFu,0xFFFFFFFFu,0xFFFFFFFFu};
__device__ unsigned g_mxk[Bb] = {0,0,0,0,0,0,0,0};

// ---------------- data scratch (fully rewritten every launch) ----------------
__device__ __align__(16) float4 g_partial[Bb][16][C4];
__device__ __align__(16) float4 g_xsum4[Bb][C4];
__device__ __align__(16) float  g_xr[Bb][Cc];
__device__ __align__(16) float  g_ksum[Bb][Cc];
__device__ __align__(16) float  g_wpart[16][Bb][Cc];
__device__ __align__(16) float  g_w[Bb][Cc];
__device__ __align__(16) float  g_upart[16][Bb][Cc];

__device__ __forceinline__ unsigned ldv(const unsigned* p) {
    return *(volatile const unsigned*)p;
}
__device__ __forceinline__ unsigned enc(float f) {
    unsigned u = __float_as_uint(f);
    return (u & 0x80000000u) ? ~u : (u | 0x80000000u);
}
__device__ __forceinline__ float dec(unsigned k) {
    return (k & 0x80000000u) ? __uint_as_float(k ^ 0x80000000u)
                             : __uint_as_float(~k);
}

// arrive: t==0 (after block sync) releases + bumps one line
#define ARRIVE_LINE(lineptr)                                          \
    do { __syncthreads();                                             \
         if (t == 0) { __threadfence(); atomicAdd(&(lineptr)->v, 1u); } \
    } while (0)
// wait until sum of n lines >= tgt
#define WAIT_LINES(arr, n, tgt)                                       \
    do { if (t == 0) {                                                \
             unsigned s_;                                             \
             do { s_ = 0;                                             \
                  _Pragma("unroll")                                   \
                  for (int i_ = 0; i_ < (n); ++i_) s_ += ldv(&(arr)[i_].v); \
             } while (s_ < (unsigned)(tgt));                          \
             __threadfence();                                         \
         }                                                            \
         __syncthreads();                                             \
    } while (0)

__global__ void __launch_bounds__(NTHR)
fused_kernel(const float* __restrict__ x,
             const float* __restrict__ conv_w, const float* __restrict__ conv_b,
             const float* __restrict__ q_w,
             const float* __restrict__ k_w,    const float* __restrict__ k_b,
             float* __restrict__ out)
{
    extern __shared__ float dynsh[];
    float* wbuf = dynsh;                         // 16384 floats (64 KB)
    float* psum = dynsh + 16384;                 // 8192 floats (32 KB): [64][128]
    __shared__ __align__(16) float shA[Bb][Cc];  // 16 KB
    __shared__ __align__(16) float shB[Cc];      // 2 KB
    __shared__ float sdot[64];
    __shared__ float shW[Bb][32];

    const int g    = blockIdx.x;
    const int t    = threadIdx.x;
    const int warp = t >> 5, lane = t & 31;
    const int b_own = g >> 4, s_own = g & 15;
    const int c4 = t & 127, rs = t >> 7;

    // ================= P1: x tile -> REGISTERS (+colsum) & weight prefetch ===
    float4 xreg[16];
    {
        const float4* base = reinterpret_cast<const float4*>(x)
                           + ((size_t)(b_own * HW + s_own * 64 + rs * 16)) * C4 + c4;
        float4 acc = make_float4(0.f, 0.f, 0.f, 0.f);
#pragma unroll
        for (int p = 0; p < 16; ++p) {
            xreg[p] = base[(size_t)p * C4];
            acc.x += xreg[p].x; acc.y += xreg[p].y;
            acc.z += xreg[p].z; acc.w += xreg[p].w;
        }
        float4* shP = reinterpret_cast<float4*>(shA);   // [4][128]
        shP[rs * C4 + c4] = acc;

        // weight prefetch into smem (overlaps x loads)
        float4* wb4 = reinterpret_cast<float4*>(wbuf);
        if (g >= 32 && g < 64) {            // A: conv_w rows [(g-32)*16, +16)
            const float4* src = reinterpret_cast<const float4*>(conv_w) + (g - 32) * 2048;
#pragma unroll
            for (int i = 0; i < 4; ++i) wb4[t + i * NTHR] = src[t + i * NTHR];
        } else if (g >= 64 && g < 96) {     // B: k_w rows [(g-64)*16, +16)
            const float4* src = reinterpret_cast<const float4*>(k_w) + (g - 64) * 2048;
#pragma unroll
            for (int i = 0; i < 4; ++i) wb4[t + i * NTHR] = src[t + i * NTHR];
        } else if (g < 16) {                // C: q_w rows [g*32, +32)
            const float4* src = reinterpret_cast<const float4*>(q_w) + g * 4096;
#pragma unroll
            for (int i = 0; i < 8; ++i) wb4[t + i * NTHR] = src[t + i * NTHR];
        } else if (g >= 16 && g < 32) {     // D: conv_w rows [(g-16)*32, +32)
            const float4* src = reinterpret_cast<const float4*>(conv_w) + (g - 16) * 4096;
#pragma unroll
            for (int i = 0; i < 8; ++i) wb4[t + i * NTHR] = src[t + i * NTHR];
        }
        __syncthreads();
        if (t < C4) {
            float4* shP2 = reinterpret_cast<float4*>(shA);
            float4 a = shP2[t], p1 = shP2[C4 + t], p2 = shP2[2 * C4 + t], p3 = shP2[3 * C4 + t];
            a.x += p1.x + p2.x + p3.x;  a.y += p1.y + p2.y + p3.y;
            a.z += p1.z + p2.z + p3.z;  a.w += p1.w + p2.w + p3.w;
            g_partial[b_own][s_own][t] = a;
        }
    }
    ARRIVE_LINE(&cnt0[b_own]);

    // ================= group A (32..63): Xsum reduce + conv matvec ===========
    if (g >= 32 && g < 64) {
        const int a = g - 32;
        WAIT_LINES(&cnt0[a >> 2], 1, 16);    // only needs its batch's partials
        {   // P2a: float4 outputs o in [a*32, a*32+32), all in batch a>>2
            const int o = a * 32 + (t >> 4), s = t & 15;
            const int bb = o >> 7, cc4 = o & 127;
            float4 v = g_partial[bb][s][cc4];
#pragma unroll
            for (int off = 8; off; off >>= 1) {
                v.x += __shfl_xor_sync(0xffffffffu, v.x, off);
                v.y += __shfl_xor_sync(0xffffffffu, v.y, off);
                v.z += __shfl_xor_sync(0xffffffffu, v.z, off);
                v.w += __shfl_xor_sync(0xffffffffu, v.w, off);
            }
            if (s == 0) g_xsum4[bb][cc4] = v;
        }
        ARRIVE_LINE(&cnt1[a & 3]);
        WAIT_LINES(cnt1, 4, 32);
        {   // P2b: xr = conv_w @ Xsum + HW*conv_b + Xsum
            float4* shA4 = reinterpret_cast<float4*>(shA);
            const float4* gx4 = reinterpret_cast<const float4*>(g_xsum4);
#pragma unroll
            for (int i = 0; i < 2; ++i) shA4[t + i * NTHR] = gx4[t + i * NTHR];
            __syncthreads();

            const int o = a * 16 + warp;
            float acc[Bb];
#pragma unroll
            for (int b = 0; b < Bb; ++b) acc[b] = 0.f;
#pragma unroll
            for (int k = 0; k < 16; ++k) {
                const int c = lane + 32 * k;
                const float wv = wbuf[warp * Cc + c];
#pragma unroll
                for (int b = 0; b < Bb; ++b) acc[b] += wv * shA[b][c];
            }
#pragma unroll
            for (int b = 0; b < Bb; ++b)
#pragma unroll
                for (int off = 16; off; off >>= 1)
                    acc[b] += __shfl_xor_sync(0xffffffffu, acc[b], off);
            if (lane == 0) {
                const float cb = (float)HW * conv_b[o];
#pragma unroll
                for (int b = 0; b < Bb; ++b)
                    g_xr[b][o] = acc[b] + cb + shA[b][o];
            }
        }
        ARRIVE_LINE(&cnt2[a & 3]);
    }

    // ================= group B (64..95): Ksum matvec =========================
    if (g >= 64 && g < 96) {
        const int bbk = g - 64;
        WAIT_LINES(cnt2, 4, 32);
        {
            float4* shA4 = reinterpret_cast<float4*>(shA);
            const float4* gxr4 = reinterpret_cast<const float4*>(g_xr);
#pragma unroll
            for (int i = 0; i < 2; ++i) shA4[t + i * NTHR] = gxr4[t + i * NTHR];
            __syncthreads();

            const int o = bbk * 16 + warp;
            float acc[Bb];
#pragma unroll
            for (int b = 0; b < Bb; ++b) acc[b] = 0.f;
#pragma unroll
            for (int k = 0; k < 16; ++k) {
                const int c = lane + 32 * k;
                const float wv = wbuf[warp * Cc + c];
#pragma unroll
                for (int b = 0; b < Bb; ++b) acc[b] += wv * shA[b][c];
            }
#pragma unroll
            for (int b = 0; b < Bb; ++b)
#pragma unroll
                for (int off = 16; off; off >>= 1)
                    acc[b] += __shfl_xor_sync(0xffffffffu, acc[b], off);
            if (lane == 0) {
                const float kb = (float)HW * k_b[o];
#pragma unroll
                for (int b = 0; b < Bb; ++b)
                    g_ksum[b][o] = acc[b] + kb;
            }
        }
        ARRIVE_LINE(&cnt3[bbk & 3]);
    }

    // ================= group C (0..15): w partials ===========================
    if (g < 16) {
        WAIT_LINES(cnt3, 4, 32);
        float tot = 0.f;
#pragma unroll
        for (int b = 0; b < Bb; ++b) tot += g_ksum[b][t];
        shB[t] = tot;
        __syncthreads();
#pragma unroll
        for (int i = 0; i < Bb; ++i) {
            const int idx = t + i * NTHR;
            const int b = idx >> 9, c = idx & 511;
            shA[b][c] = shB[c] - g_ksum[b][c];
        }
        __syncthreads();

        float acc[Bb];
#pragma unroll
        for (int b = 0; b < Bb; ++b) acc[b] = 0.f;
#pragma unroll
        for (int oo = 0; oo < 32; ++oo) {
            const int o = g * 32 + oo;
            const float wv = wbuf[oo * Cc + t];
#pragma unroll
            for (int b = 0; b < Bb; ++b) acc[b] += wv * shA[b][o];
        }
#pragma unroll
        for (int b = 0; b < Bb; ++b) g_wpart[g][b][t] = acc[b];
        ARRIVE_LINE(&cnt4[g & 1]);
    }

    // ================= group D (16..31): w reduce (o-chunk) + u partial ======
    if (g >= 16 && g < 32) {
        const int j = g - 16;
        WAIT_LINES(cnt4, 2, 16);
        {   // inline reduce of w over its o-chunk [j*32, +32), all b
            const int p = t >> 1, h = t & 1;       // p: 0..255 = (b,oo)
            const int b = p >> 5, oo = p & 31;
            float s = 0.f;
#pragma unroll
            for (int jj = 0; jj < 8; ++jj)
                s += g_wpart[h * 8 + jj][b][j * 32 + oo];
            s += __shfl_xor_sync(0xffffffffu, s, 1);
            if (h == 0) { shW[b][oo] = s; g_w[b][j * 32 + oo] = s; }
            __syncthreads();
        }
        {   // u partial: conv_w^T over o-chunk
            float acc[Bb];
#pragma unroll
            for (int b = 0; b < Bb; ++b) acc[b] = 0.f;
#pragma unroll
            for (int oo = 0; oo < 32; ++oo) {
                const float wv = wbuf[oo * Cc + t];
#pragma unroll
                for (int b = 0; b < Bb; ++b) acc[b] += wv * shW[b][oo];
            }
#pragma unroll
            for (int b = 0; b < Bb; ++b) g_upart[j][b][t] = acc[b];
        }
        ARRIVE_LINE(&cnt6[0]);
    }

    // ================= all blocks: P6 dot + epilogue =========================
    WAIT_LINES(cnt6, 1, 16);
    {
        // u[t] = sum_j upart[j][b][t] + w[b][t]   (the +w residual term)
        float a = g_w[b_own][t];
#pragma unroll
        for (int jj = 0; jj < 16; ++jj) a += g_upart[jj][b_own][t];
        shB[t] = a;
        __syncthreads();

        const float4 uv = reinterpret_cast<const float4*>(shB)[c4];
#pragma unroll
        for (int p = 0; p < 16; ++p) {
            const float4 xv = xreg[p];
            psum[(rs * 16 + p) * C4 + c4] =
                xv.x * uv.x + xv.y * uv.y + xv.z * uv.z + xv.w * uv.w;
        }
        __syncthreads();

        // row reduce: warp handles 4 rows, 128 partials each
#pragma unroll
        for (int rr = 0; rr < 4; ++rr) {
            const int row = warp * 4 + rr;
            float s = psum[row * C4 + lane] + psum[row * C4 + lane + 32]
                    + psum[row * C4 + lane + 64] + psum[row * C4 + lane + 96];
#pragma unroll
            for (int off = 16; off; off >>= 1)
                s += __shfl_xor_sync(0xffffffffu, s, off);
            if (lane == 0) sdot[row] = s;
        }
    }
    __syncthreads();
    if (warp == 0) {
        float v0 = sdot[lane], v1 = sdot[lane + 32];
        float mn = fminf(v0, v1), mx = fmaxf(v0, v1);
#pragma unroll
        for (int off = 16; off; off >>= 1) {
            mn = fminf(mn, __shfl_xor_sync(0xffffffffu, mn, off));
            mx = fmaxf(mx, __shfl_xor_sync(0xffffffffu, mx, off));
        }
        if (lane == 0) {
            atomicMin(&g_mnk[b_own], enc(mn));
            atomicMax(&g_mxk[b_own], enc(mx));
        }
    }
    ARRIVE_LINE(&cnt7[b_own]);
    WAIT_LINES(&cnt7[b_own], 1, 16);

    if (t < 64) {
        const float mn = dec(g_mnk[b_own]);
        const float mx = dec(g_mxk[b_own]);
        const float inv = 1.0f / (mx - mn);
        const float z = ((sdot[t] - mn) * inv - 0.65f) / 0.15f;
        out[b_own * HW + s_own * 64 + t] = 1.0f / (1.0f + __expf(-z));
    }

    // final ack + reset by block 0 (all pollers are past all counters now)
    ARRIVE_LINE(&cnt8[g & 15]);
    if (g == 0 && t == 0) {
        unsigned s;
        do { s = 0;
#pragma unroll
             for (int i = 0; i < 16; ++i) s += ldv(&cnt8[i].v);
        } while (s < (unsigned)NBLK);
#pragma unroll
        for (int i = 0; i < 8;  ++i) cnt0[i].v = 0u;
#pragma unroll
        for (int i = 0; i < 4;  ++i) { cnt1[i].v = 0u; cnt2[i].v = 0u; cnt3[i].v = 0u; }
#pragma unroll
        for (int i = 0; i < 2;  ++i) cnt4[i].v = 0u;
        cnt6[0].v = 0u;
#pragma unroll
        for (int i = 0; i < 8;  ++i) cnt7[i].v = 0u;
#pragma unroll
        for (int i = 0; i < 16; ++i) cnt8[i].v = 0u;
#pragma unroll
        for (int b = 0; b < Bb; ++b) { g_mnk[b] = 0xFFFFFFFFu; g_mxk[b] = 0u; }
        __threadfence();
    }
}

// ---------------------------------------------------------------------------
extern "C" void kernel_launch(void* const* d_in, const int* in_sizes, int n_in,
                              void* d_out, int out_size) {
    const float* x      = (const float*)d_in[0];
    const float* conv_w = (const float*)d_in[1];
    const float* conv_b = (const float*)d_in[2];
    const float* q_w    = (const float*)d_in[3];
    // d_in[4] = q_b: per-batch constant, cancels in min/max normalization.
    const float* k_w    = (const float*)d_in[5];
    const float* k_b    = (const float*)d_in[6];
    float* out = (float*)d_out;

    cudaFuncSetAttribute(fused_kernel,
                         cudaFuncAttributeMaxDynamicSharedMemorySize,
                         DYN_BYTES);
    fused_kernel<<<NBLK, NTHR, DYN_BYTES>>>(x, conv_w, conv_b, q_w, k_w, k_b, out);
}